// round 4
// baseline (speedup 1.0000x reference)
#include <cuda_runtime.h>
#include <cuda_fp16.h>
#include <cstdint>

#define BATCH 32
#define HH 512
#define WW 512
#define NPX (BATCH * HH * WW)

#define TX 64  // output tile width
#define TY 64  // output tile height
#define SW 72  // smem tile width  (TX + 8)
#define SH 72  // smem tile height (TY + 8)

// 9x9 kernel weights in constant bank
__constant__ float c_w[81];

// Scratch (device globals: allocation-free per harness rules)
__device__ __half g_lm[NPX];   // local mean, fp16
__device__ __half g_s2[NPX];   // channel-mean squared-dev, fp16
__device__ __half g_sig[NPX];  // sigma, fp16 (only feeds max() denominator)
__device__ float  g_part[BATCH * 64];

typedef unsigned long long u64;

// --- f32x2 packed-math helpers (Blackwell FFMA2 path) ----------------------
__device__ __forceinline__ u64 bcast2(float w) {
    u64 r;
    asm("mov.b64 %0, {%1, %1};" : "=l"(r) : "r"(__float_as_uint(w)));
    return r;
}
__device__ __forceinline__ void fma2(u64& acc, u64 a, u64 b) {
    asm("fma.rn.f32x2 %0, %1, %2, %0;" : "+l"(acc) : "l"(a), "l"(b));
}
__device__ __forceinline__ u64 lds64(uint32_t a) {
    u64 v;
    asm volatile("ld.shared.b64 %0, [%1];" : "=l"(v) : "r"(a));
    return v;
}

// ---------------------------------------------------------------------------
// Blur core: block (32,8). Thread = 2 adjacent cols (2tx, 2tx+1) x 8 rows.
// Even taps read the aligned tile, odd taps the 1-element-shifted copy ->
// every access is an aligned, conflict-free LDS.64. Outer k-loop rolled:
// 9 broadcast weight pairs live in regs per iteration (81 LDC total/thread).
// ---------------------------------------------------------------------------
__device__ __forceinline__ void blur64(uint32_t smb, uint32_t smSb,
                                       int tx, int tz, u64 acc[8]) {
#pragma unroll
    for (int i = 0; i < 8; i++) acc[i] = 0ull;

#pragma unroll 1
    for (int k = 0; k < 9; k += 2) {  // even taps
        u64 w2[9];
#pragma unroll
        for (int ky = 0; ky < 9; ky++) w2[ky] = bcast2(c_w[ky * 9 + k]);
        uint32_t a0 = smb + (uint32_t)(((8 * tz) * SW + 2 * tx + k) * 4);
#pragma unroll
        for (int j = 0; j < 16; j++) {
            u64 pr = lds64(a0 + j * (SW * 4));
#pragma unroll
            for (int oy = 0; oy < 8; oy++) {
                int ky = j - oy;
                if (ky >= 0 && ky < 9) fma2(acc[oy], w2[ky], pr);
            }
        }
    }
#pragma unroll 1
    for (int k = 1; k < 9; k += 2) {  // odd taps via shifted copy
        u64 w2[9];
#pragma unroll
        for (int ky = 0; ky < 9; ky++) w2[ky] = bcast2(c_w[ky * 9 + k]);
        uint32_t a0 = smSb + (uint32_t)(((8 * tz) * SW + 2 * tx + (k - 1)) * 4);
#pragma unroll
        for (int j = 0; j < 16; j++) {
            u64 pr = lds64(a0 + j * (SW * 4));
#pragma unroll
            for (int oy = 0; oy < 8; oy++) {
                int ky = j - oy;
                if (ky >= 0 && ky < 9) fma2(acc[oy], w2[ky], pr);
            }
        }
    }
}

// ---------------------------------------------------------------------------
// Stage 1: load x tile (72x72 px, 3ch), build m (aligned + shifted, f32) and
// q (fp16) tiles, blur m -> lm, s2 = q - 2*lm*m + lm^2. Write lm, s2 half2.
// Dynamic smem: 2*20736 (f32) + 10368 (half) = 51840 B -> 4 CTA/SM.
// ---------------------------------------------------------------------------
__global__ __launch_bounds__(256) void k_stage1(const float* __restrict__ x) {
    extern __shared__ float dsm[];
    float*  sm  = dsm;                                  // [SH][SW] f32
    float*  smS = dsm + SH * SW;                        // shifted copy f32
    __half* sq  = (__half*)(dsm + 2 * SH * SW);         // [SH][SW] fp16

    const int b = blockIdx.z;
    const int x0 = blockIdx.x * TX, y0 = blockIdx.y * TY;
    const int tid = threadIdx.y * 32 + threadIdx.x;
    const float inv3 = 1.f / 3.f;

    for (int i = tid; i < SH * SW; i += 256) {
        int r = i / SW, c = i - r * SW;
        int gy = y0 - 4 + r, gx = x0 - 4 + c;
        float m = 0.f, q = 0.f;
        if ((unsigned)gy < (unsigned)HH && (unsigned)gx < (unsigned)WW) {
            const float* p = x + ((size_t)(b * HH + gy) * WW + gx) * 3;
            float a0 = __ldcs(p), a1 = __ldcs(p + 1), a2 = __ldcs(p + 2);
            m = (a0 + a1 + a2) * inv3;
            q = fmaf(a0, a0, fmaf(a1, a1, a2 * a2)) * inv3;
        }
        sm[i] = m;
        sq[i] = __float2half_rn(q);
        if (c > 0) smS[i - 1] = m;
    }
    __syncthreads();

    const int tx = threadIdx.x, tz = threadIdx.y;
    uint32_t smb  = (uint32_t)__cvta_generic_to_shared(sm);
    uint32_t smSb = (uint32_t)__cvta_generic_to_shared(smS);
    u64 acc[8];
    blur64(smb, smSb, tx, tz, acc);

#pragma unroll
    for (int oy = 0; oy < 8; oy++) {
        float lm0 = __uint_as_float((uint32_t)acc[oy]);
        float lm1 = __uint_as_float((uint32_t)(acc[oy] >> 32));
        int si = (8 * tz + oy + 4) * SW + 2 * tx + 4;
        float m0 = sm[si], m1 = sm[si + 1];
        float q0 = __half2float(sq[si]), q1 = __half2float(sq[si + 1]);
        // s2 = q - 2*lm*m + lm^2 = fma(lm, lm - 2m, q)
        float s20 = fmaxf(fmaf(lm0, fmaf(-2.f, m0, lm0), q0), 0.f);
        float s21 = fmaxf(fmaf(lm1, fmaf(-2.f, m1, lm1), q1), 0.f);
        int idx = (b * HH + y0 + 8 * tz + oy) * WW + x0 + 2 * tx;
        __stcs((__half2*)&g_lm[idx], __floats2half2_rn(lm0, lm1));
        __stcs((__half2*)&g_s2[idx], __floats2half2_rn(s20, s21));
    }
}

// ---------------------------------------------------------------------------
// Stage 2: blur s2 -> sigma = sqrt(.), write sigma fp16 + per-block partials.
// ---------------------------------------------------------------------------
__global__ __launch_bounds__(256) void k_stage2() {
    __shared__ __align__(16) float ss[SH][SW];
    __shared__ __align__(16) float ssS[SH][SW];
    __shared__ float warpsum[8];

    const int b = blockIdx.z;
    const int x0 = blockIdx.x * TX, y0 = blockIdx.y * TY;
    const int tid = threadIdx.y * 32 + threadIdx.x;

    for (int i = tid; i < SH * SW; i += 256) {
        int r = i / SW, c = i - r * SW;
        int gy = y0 - 4 + r, gx = x0 - 4 + c;
        float s = 0.f;
        if ((unsigned)gy < (unsigned)HH && (unsigned)gx < (unsigned)WW)
            s = __half2float(g_s2[(b * HH + gy) * WW + gx]);
        ss[r][c] = s;
        if (c > 0) ssS[r][c - 1] = s;
    }
    __syncthreads();

    const int tx = threadIdx.x, tz = threadIdx.y;
    uint32_t smb  = (uint32_t)__cvta_generic_to_shared(&ss[0][0]);
    uint32_t smSb = (uint32_t)__cvta_generic_to_shared(&ssS[0][0]);
    u64 acc[8];
    blur64(smb, smSb, tx, tz, acc);

    float lsum = 0.f;
#pragma unroll
    for (int oy = 0; oy < 8; oy++) {
        float s0 = sqrtf(fmaxf(__uint_as_float((uint32_t)acc[oy]), 0.f));
        float s1 = sqrtf(fmaxf(__uint_as_float((uint32_t)(acc[oy] >> 32)), 0.f));
        int idx = (b * HH + y0 + 8 * tz + oy) * WW + x0 + 2 * tx;
        __stcs((__half2*)&g_sig[idx], __floats2half2_rn(s0, s1));
        lsum += s0 + s1;
    }

#pragma unroll
    for (int o = 16; o > 0; o >>= 1)
        lsum += __shfl_down_sync(0xFFFFFFFFu, lsum, o);
    if (tx == 0) warpsum[tz] = lsum;
    __syncthreads();
    if (tid == 0) {
        float t = 0.f;
#pragma unroll
        for (int i = 0; i < 8; i++) t += warpsum[i];
        g_part[b * 64 + blockIdx.y * 8 + blockIdx.x] = t;
    }
}

// ---------------------------------------------------------------------------
// Final: prologue re-reduces this batch's 64 partials (L2 hits) -> ms, then
// out = (x - lm) / max(ms, sigma). 8 px / thread, streaming float4 traffic.
// 128 blocks per batch image (2^18 px / 2048).
// ---------------------------------------------------------------------------
__global__ __launch_bounds__(256) void k_final(const float* __restrict__ x,
                                               float* __restrict__ out) {
    __shared__ float s_w[2];
    __shared__ float s_ms;

    const int b = blockIdx.x >> 7;  // 128 blocks / batch
    if (threadIdx.x < 64) {
        float v = g_part[b * 64 + threadIdx.x];
#pragma unroll
        for (int o = 16; o > 0; o >>= 1)
            v += __shfl_down_sync(0xFFFFFFFFu, v, o);
        if ((threadIdx.x & 31) == 0) s_w[threadIdx.x >> 5] = v;
    }
    __syncthreads();
    if (threadIdx.x == 0)
        s_ms = (s_w[0] + s_w[1]) * (1.f / ((float)HH * (float)WW));
    __syncthreads();
    const float ms = s_ms;

    const int p = (blockIdx.x & 127) * 2048 + threadIdx.x * 8 + (b << 18);

    uint4 lmu = __ldcs((const uint4*)((const __half*)g_lm + p));
    uint4 sgu = __ldcs((const uint4*)((const __half*)g_sig + p));
    const __half2* lmh = (const __half2*)&lmu;
    const __half2* sgh = (const __half2*)&sgu;

    const float4* xp = (const float4*)(x + (size_t)p * 3);
    float4 xv[6];
#pragma unroll
    for (int i = 0; i < 6; i++) xv[i] = __ldcs(xp + i);

    float lmv[8], inv[8];
#pragma unroll
    for (int i = 0; i < 4; i++) {
        float2 l = __half22float2(lmh[i]);
        float2 s = __half22float2(sgh[i]);
        lmv[2 * i] = l.x;
        lmv[2 * i + 1] = l.y;
        inv[2 * i] = __frcp_rn(fmaxf(ms, s.x));
        inv[2 * i + 1] = __frcp_rn(fmaxf(ms, s.y));
    }

    const float* f = (const float*)xv;
    float4* op = (float4*)(out + (size_t)p * 3);
#pragma unroll
    for (int i = 0; i < 6; i++) {
        float o0 = (f[4 * i + 0] - lmv[(4 * i + 0) / 3]) * inv[(4 * i + 0) / 3];
        float o1 = (f[4 * i + 1] - lmv[(4 * i + 1) / 3]) * inv[(4 * i + 1) / 3];
        float o2 = (f[4 * i + 2] - lmv[(4 * i + 2) / 3]) * inv[(4 * i + 2) / 3];
        float o3 = (f[4 * i + 3] - lmv[(4 * i + 3) / 3]) * inv[(4 * i + 3) / 3];
        __stcs(op + i, make_float4(o0, o1, o2, o3));
    }
}

// ---------------------------------------------------------------------------
extern "C" void kernel_launch(void* const* d_in, const int* in_sizes, int n_in,
                              void* d_out, int out_size) {
    const float* x = (const float*)d_in[0];

    cudaMemcpyToSymbolAsync(c_w, d_in[1], 81 * sizeof(float), 0,
                            cudaMemcpyDeviceToDevice, 0);

    const int smem1 = (2 * SH * SW) * (int)sizeof(float) +
                      SH * SW * (int)sizeof(__half);  // 51840 B
    cudaFuncSetAttribute(k_stage1, cudaFuncAttributeMaxDynamicSharedMemorySize,
                         smem1);

    dim3 blk(32, 8);
    dim3 grd(WW / TX, HH / TY, BATCH);
    k_stage1<<<grd, blk, smem1>>>(x);
    k_stage2<<<grd, blk>>>();
    k_final<<<BATCH * 128, 256>>>(x, (float*)d_out);
}

// round 5
// speedup vs baseline: 1.0467x; 1.0467x over previous
#include <cuda_runtime.h>
#include <cuda_fp16.h>
#include <cstdint>

#define BATCH 32
#define HH 512
#define WW 512
#define NPX (BATCH * HH * WW)

#define TX 64  // output tile width
#define TY 64  // output tile height
#define SW 72  // smem tile width  (TX + 8)
#define SH 72  // smem tile height (TY + 8)

// 9x9 kernel weights in constant bank
__constant__ float c_w[81];

// Scratch (device globals: allocation-free per harness rules)
__device__ __half g_lm[NPX];   // local mean, fp16
__device__ __half g_s2[NPX];   // channel-mean squared-dev, fp16
__device__ __half g_sig[NPX];  // sigma, fp16
__device__ float  g_part[BATCH * 64];

typedef unsigned long long u64;

// --- f32x2 packed-math helpers (Blackwell FFMA2 path) ----------------------
__device__ __forceinline__ u64 bcast2(float w) {
    u64 r;
    asm("mov.b64 %0, {%1, %1};" : "=l"(r) : "r"(__float_as_uint(w)));
    return r;
}
__device__ __forceinline__ void fma2(u64& acc, u64 a, u64 b) {
    asm("fma.rn.f32x2 %0, %1, %2, %0;" : "+l"(acc) : "l"(a), "l"(b));
}
__device__ __forceinline__ u64 lds64(uint32_t a) {
    u64 v;
    asm volatile("ld.shared.b64 %0, [%1];" : "=l"(v) : "r"(a));
    return v;
}

// ---------------------------------------------------------------------------
// Blur core: block (32,8). Thread = 2 adjacent cols x 8 rows. Even taps read
// the aligned tile, odd taps the 1-element-shifted copy -> aligned LDS.64,
// conflict-free. Per tap-column we BATCH all 16 row loads into v[16] before
// consuming (MLP=16, hides the 29-cyc LDS latency that capped issue at 55%).
// ---------------------------------------------------------------------------
__device__ __forceinline__ void blur64(uint32_t smb, uint32_t smSb,
                                       int tx, int tz, u64 acc[8]) {
#pragma unroll
    for (int i = 0; i < 8; i++) acc[i] = 0ull;

#pragma unroll 1
    for (int k = 0; k < 9; k += 2) {  // even taps
        u64 w2[9];
#pragma unroll
        for (int ky = 0; ky < 9; ky++) w2[ky] = bcast2(c_w[ky * 9 + k]);
        uint32_t a0 = smb + (uint32_t)(((8 * tz) * SW + 2 * tx + k) * 4);
        u64 v[16];
#pragma unroll
        for (int j = 0; j < 16; j++) v[j] = lds64(a0 + j * (SW * 4));
#pragma unroll
        for (int j = 0; j < 16; j++) {
#pragma unroll
            for (int oy = 0; oy < 8; oy++) {
                int ky = j - oy;
                if (ky >= 0 && ky < 9) fma2(acc[oy], w2[ky], v[j]);
            }
        }
    }
#pragma unroll 1
    for (int k = 1; k < 9; k += 2) {  // odd taps via shifted copy
        u64 w2[9];
#pragma unroll
        for (int ky = 0; ky < 9; ky++) w2[ky] = bcast2(c_w[ky * 9 + k]);
        uint32_t a0 = smSb + (uint32_t)(((8 * tz) * SW + 2 * tx + (k - 1)) * 4);
        u64 v[16];
#pragma unroll
        for (int j = 0; j < 16; j++) v[j] = lds64(a0 + j * (SW * 4));
#pragma unroll
        for (int j = 0; j < 16; j++) {
#pragma unroll
            for (int oy = 0; oy < 8; oy++) {
                int ky = j - oy;
                if (ky >= 0 && ky < 9) fma2(acc[oy], w2[ky], v[j]);
            }
        }
    }
}

// ---------------------------------------------------------------------------
// Stage 1: load x tile (72x72 px, 3ch), build m (f32, aligned + shifted) and
// q (fp16) tiles; blur m -> lm; s2 = q - 2*lm*m + lm^2. Write lm, s2 half2.
// Fill loop uses incremental (r,c) — no divisions.
// ---------------------------------------------------------------------------
__global__ __launch_bounds__(256, 3) void k_stage1(const float* __restrict__ x) {
    extern __shared__ float dsm[];
    float*  sm  = dsm;                           // [SH][SW] f32
    float*  smS = dsm + SH * SW;                 // shifted copy f32
    __half* sq  = (__half*)(dsm + 2 * SH * SW);  // [SH][SW] fp16

    const int b = blockIdx.z;
    const int x0 = blockIdx.x * TX, y0 = blockIdx.y * TY;
    const int tid = threadIdx.y * 32 + threadIdx.x;
    const float inv3 = 1.f / 3.f;

    {
        int r = tid / SW, c = tid - r * SW;  // once
        for (int i = tid; i < SH * SW; i += 256) {
            int gy = y0 - 4 + r, gx = x0 - 4 + c;
            float m = 0.f, q = 0.f;
            if ((unsigned)gy < (unsigned)HH && (unsigned)gx < (unsigned)WW) {
                const float* p = x + ((size_t)(b * HH + gy) * WW + gx) * 3;
                float a0 = __ldcs(p), a1 = __ldcs(p + 1), a2 = __ldcs(p + 2);
                m = (a0 + a1 + a2) * inv3;
                q = fmaf(a0, a0, fmaf(a1, a1, a2 * a2)) * inv3;
            }
            sm[i] = m;
            sq[i] = __float2half_rn(q);
            if (c > 0) smS[i - 1] = m;
            // advance (r,c) by 256 = 3*SW + 40
            c += 256 - 3 * SW;
            r += 3;
            if (c >= SW) { c -= SW; r += 1; }
        }
    }
    __syncthreads();

    const int tx = threadIdx.x, tz = threadIdx.y;
    uint32_t smb  = (uint32_t)__cvta_generic_to_shared(sm);
    uint32_t smSb = (uint32_t)__cvta_generic_to_shared(smS);
    u64 acc[8];
    blur64(smb, smSb, tx, tz, acc);

#pragma unroll
    for (int oy = 0; oy < 8; oy++) {
        float lm0 = __uint_as_float((uint32_t)acc[oy]);
        float lm1 = __uint_as_float((uint32_t)(acc[oy] >> 32));
        int si = (8 * tz + oy + 4) * SW + 2 * tx + 4;
        float m0 = sm[si], m1 = sm[si + 1];
        float q0 = __half2float(sq[si]), q1 = __half2float(sq[si + 1]);
        float s20 = fmaxf(fmaf(lm0, fmaf(-2.f, m0, lm0), q0), 0.f);
        float s21 = fmaxf(fmaf(lm1, fmaf(-2.f, m1, lm1), q1), 0.f);
        int idx = (b * HH + y0 + 8 * tz + oy) * WW + x0 + 2 * tx;
        __stcs((__half2*)&g_lm[idx], __floats2half2_rn(lm0, lm1));
        __stcs((__half2*)&g_s2[idx], __floats2half2_rn(s20, s21));
    }
}

// ---------------------------------------------------------------------------
// Stage 2: blur s2 -> sigma = sqrt(.), write sigma fp16 + per-block partials.
// ---------------------------------------------------------------------------
__global__ __launch_bounds__(256, 3) void k_stage2() {
    __shared__ __align__(16) float ss[SH][SW];
    __shared__ __align__(16) float ssS[SH][SW];
    __shared__ float warpsum[8];

    const int b = blockIdx.z;
    const int x0 = blockIdx.x * TX, y0 = blockIdx.y * TY;
    const int tid = threadIdx.y * 32 + threadIdx.x;

    {
        int r = tid / SW, c = tid - r * SW;
        for (int i = tid; i < SH * SW; i += 256) {
            int gy = y0 - 4 + r, gx = x0 - 4 + c;
            float s = 0.f;
            if ((unsigned)gy < (unsigned)HH && (unsigned)gx < (unsigned)WW)
                s = __half2float(g_s2[(b * HH + gy) * WW + gx]);
            ((float*)ss)[i] = s;
            if (c > 0) ((float*)ssS)[i - 1] = s;
            c += 256 - 3 * SW;
            r += 3;
            if (c >= SW) { c -= SW; r += 1; }
        }
    }
    __syncthreads();

    const int tx = threadIdx.x, tz = threadIdx.y;
    uint32_t smb  = (uint32_t)__cvta_generic_to_shared(&ss[0][0]);
    uint32_t smSb = (uint32_t)__cvta_generic_to_shared(&ssS[0][0]);
    u64 acc[8];
    blur64(smb, smSb, tx, tz, acc);

    float lsum = 0.f;
#pragma unroll
    for (int oy = 0; oy < 8; oy++) {
        float s0 = sqrtf(fmaxf(__uint_as_float((uint32_t)acc[oy]), 0.f));
        float s1 = sqrtf(fmaxf(__uint_as_float((uint32_t)(acc[oy] >> 32)), 0.f));
        int idx = (b * HH + y0 + 8 * tz + oy) * WW + x0 + 2 * tx;
        __stcs((__half2*)&g_sig[idx], __floats2half2_rn(s0, s1));
        lsum += s0 + s1;
    }

#pragma unroll
    for (int o = 16; o > 0; o >>= 1)
        lsum += __shfl_down_sync(0xFFFFFFFFu, lsum, o);
    if (tx == 0) warpsum[tz] = lsum;
    __syncthreads();
    if (tid == 0) {
        float t = 0.f;
#pragma unroll
        for (int i = 0; i < 8; i++) t += warpsum[i];
        g_part[b * 64 + blockIdx.y * 8 + blockIdx.x] = t;
    }
}

// ---------------------------------------------------------------------------
// Final: prologue re-reduces this batch's 64 partials (L2 hits) -> ms, then
// out = (x - lm) / max(ms, sigma). 8 px / thread, streaming float4 traffic.
// ---------------------------------------------------------------------------
__global__ __launch_bounds__(256) void k_final(const float* __restrict__ x,
                                               float* __restrict__ out) {
    __shared__ float s_w[2];
    __shared__ float s_ms;

    const int b = blockIdx.x >> 7;  // 128 blocks / batch
    if (threadIdx.x < 64) {
        float v = g_part[b * 64 + threadIdx.x];
#pragma unroll
        for (int o = 16; o > 0; o >>= 1)
            v += __shfl_down_sync(0xFFFFFFFFu, v, o);
        if ((threadIdx.x & 31) == 0) s_w[threadIdx.x >> 5] = v;
    }
    __syncthreads();
    if (threadIdx.x == 0)
        s_ms = (s_w[0] + s_w[1]) * (1.f / ((float)HH * (float)WW));
    __syncthreads();
    const float ms = s_ms;

    const int p = (blockIdx.x & 127) * 2048 + threadIdx.x * 8 + (b << 18);

    uint4 lmu = __ldcs((const uint4*)((const __half*)g_lm + p));
    uint4 sgu = __ldcs((const uint4*)((const __half*)g_sig + p));
    const __half2* lmh = (const __half2*)&lmu;
    const __half2* sgh = (const __half2*)&sgu;

    const float4* xp = (const float4*)(x + (size_t)p * 3);
    float4 xv[6];
#pragma unroll
    for (int i = 0; i < 6; i++) xv[i] = __ldcs(xp + i);

    float lmv[8], inv[8];
#pragma unroll
    for (int i = 0; i < 4; i++) {
        float2 l = __half22float2(lmh[i]);
        float2 s = __half22float2(sgh[i]);
        lmv[2 * i] = l.x;
        lmv[2 * i + 1] = l.y;
        inv[2 * i] = __frcp_rn(fmaxf(ms, s.x));
        inv[2 * i + 1] = __frcp_rn(fmaxf(ms, s.y));
    }

    const float* f = (const float*)xv;
    float4* op = (float4*)(out + (size_t)p * 3);
#pragma unroll
    for (int i = 0; i < 6; i++) {
        float o0 = (f[4 * i + 0] - lmv[(4 * i + 0) / 3]) * inv[(4 * i + 0) / 3];
        float o1 = (f[4 * i + 1] - lmv[(4 * i + 1) / 3]) * inv[(4 * i + 1) / 3];
        float o2 = (f[4 * i + 2] - lmv[(4 * i + 2) / 3]) * inv[(4 * i + 2) / 3];
        float o3 = (f[4 * i + 3] - lmv[(4 * i + 3) / 3]) * inv[(4 * i + 3) / 3];
        __stcs(op + i, make_float4(o0, o1, o2, o3));
    }
}

// ---------------------------------------------------------------------------
extern "C" void kernel_launch(void* const* d_in, const int* in_sizes, int n_in,
                              void* d_out, int out_size) {
    const float* x = (const float*)d_in[0];

    cudaMemcpyToSymbolAsync(c_w, d_in[1], 81 * sizeof(float), 0,
                            cudaMemcpyDeviceToDevice, 0);

    const int smem1 = (2 * SH * SW) * (int)sizeof(float) +
                      SH * SW * (int)sizeof(__half);  // 51840 B
    cudaFuncSetAttribute(k_stage1, cudaFuncAttributeMaxDynamicSharedMemorySize,
                         smem1);

    dim3 blk(32, 8);
    dim3 grd(WW / TX, HH / TY, BATCH);
    k_stage1<<<grd, blk, smem1>>>(x);
    k_stage2<<<grd, blk>>>();
    k_final<<<BATCH * 128, 256>>>(x, (float*)d_out);
}